// round 15
// baseline (speedup 1.0000x reference)
#include <cuda_runtime.h>
#include <cuda_bf16.h>
#include <math.h>
#include <stdint.h>

#define N_ROWS 32768
#define IN_DIM 768
#define HID 2048
#define OUT_DIM 256
#define KCODES 1024

typedef __nv_bfloat16 bf16;

// ---- scratch (device globals) ----
__device__ bf16 g_xs1[(size_t)N_ROWS * IN_DIM], g_xs2[(size_t)N_ROWS * IN_DIM], g_xs3[(size_t)N_ROWS * IN_DIM];
__device__ bf16 g_hs1[(size_t)N_ROWS * HID], g_hs2[(size_t)N_ROWS * HID], g_hs3[(size_t)N_ROWS * HID];
__device__ bf16 g_zs1[(size_t)N_ROWS * OUT_DIM], g_zs2[(size_t)N_ROWS * OUT_DIM], g_zs3[(size_t)N_ROWS * OUT_DIM];
__device__ bf16 g_w1a[(size_t)HID * IN_DIM], g_w1b[(size_t)HID * IN_DIM], g_w1c[(size_t)HID * IN_DIM];
__device__ bf16 g_w2a[(size_t)OUT_DIM * HID], g_w2b[(size_t)OUT_DIM * HID], g_w2c[(size_t)OUT_DIM * HID];
__device__ bf16 g_d1a[(size_t)HID * OUT_DIM], g_d1b[(size_t)HID * OUT_DIM], g_d1c[(size_t)HID * OUT_DIM];
__device__ bf16 g_d2a[(size_t)IN_DIM * HID], g_d2b[(size_t)IN_DIM * HID], g_d2c[(size_t)IN_DIM * HID];
__device__ bf16 g_et1[KCODES * OUT_DIM], g_et2[KCODES * OUT_DIM], g_et3[KCODES * OUT_DIM];
__device__ float g_scores[(size_t)N_ROWS * KCODES];
__device__ float g_emb2[KCODES];
__device__ float g_rownorm[N_ROWS];

// ---- helpers ----
__device__ __forceinline__ uint32_t smem_u32(const void* p) {
    uint32_t a;
    asm("{ .reg .u64 t; cvta.to.shared.u64 t, %1; cvt.u32.u64 %0, t; }" : "=r"(a) : "l"(p));
    return a;
}
__device__ __forceinline__ uint32_t lds32(uint32_t a) {
    uint32_t v; asm volatile("ld.shared.b32 %0, [%1];" : "=r"(v) : "r"(a)); return v;
}
__device__ __forceinline__ void cpasync16(uint32_t s, const void* g) {
    asm volatile("cp.async.cg.shared.global [%0], [%1], 16;" :: "r"(s), "l"(g));
}
__device__ __forceinline__ void mma16816(float* d, const uint32_t* a, const uint32_t* b) {
    asm volatile(
        "mma.sync.aligned.m16n8k16.row.col.f32.bf16.bf16.f32 "
        "{%0,%1,%2,%3}, {%4,%5,%6,%7}, {%8,%9}, {%0,%1,%2,%3};"
        : "+f"(d[0]), "+f"(d[1]), "+f"(d[2]), "+f"(d[3])
        : "r"(a[0]), "r"(a[1]), "r"(a[2]), "r"(a[3]), "r"(b[0]), "r"(b[1]));
}
// first mma of an accumulation chain: C = 0 (no explicit zero-init needed)
__device__ __forceinline__ void mma16816_z(float* d, const uint32_t* a, const uint32_t* b) {
    asm volatile(
        "mma.sync.aligned.m16n8k16.row.col.f32.bf16.bf16.f32 "
        "{%0,%1,%2,%3}, {%4,%5,%6,%7}, {%8,%9}, {%10,%10,%10,%10};"
        : "=f"(d[0]), "=f"(d[1]), "=f"(d[2]), "=f"(d[3])
        : "r"(a[0]), "r"(a[1]), "r"(a[2]), "r"(a[3]), "r"(b[0]), "r"(b[1]),
          "f"(0.0f));
}
__device__ __forceinline__ void split3(float v, bf16& b1, bf16& b2, bf16& b3) {
    b1 = __float2bfloat16(v);
    float r = v - __bfloat162float(b1);
    b2 = __float2bfloat16(r);
    b3 = __float2bfloat16(r - __bfloat162float(b2));
}
__device__ __forceinline__ uint32_t pack2(bf16 a, bf16 b) {
    return (uint32_t)__nv_bfloat16_raw(a).x | ((uint32_t)__nv_bfloat16_raw(b).x << 16);
}

// ============ kernel 1: encoder GEMM (NP=6, 64x32 warp tile, low-cost drain) ============
// Tile 128x128x32, 256 thr, 8 warps (2x4), 3-stage ring.
// Drain every 2 chunks; chains start via mma_z (C=0) instead of zero-init.
// EPI: 0 relu->splits, 1 none->fp32+splits
template<int EPI>
__global__ void __launch_bounds__(256, 1) gemmMMA(
    const bf16* __restrict__ A1, const bf16* __restrict__ A2, const bf16* __restrict__ A3,
    const bf16* __restrict__ B1, const bf16* __restrict__ B2, const bf16* __restrict__ B3,
    const float* __restrict__ bias,
    float* __restrict__ outF, bf16* __restrict__ O1, bf16* __restrict__ O2, bf16* __restrict__ O3,
    int N, int K)
{
    constexpr int TB = 128 * 80;
    constexpr int STG = 6 * TB;
    extern __shared__ char smem[];

    const int tid = threadIdx.x, lane = tid & 31, wid = tid >> 5;
    const int wm = wid >> 2, wn = wid & 3;
    const int m0 = blockIdx.y * 128, n0 = blockIdx.x * 128;
    const uint32_t sbase = smem_u32(smem);
    const int lg = lane >> 2, lk = (lane & 3) * 2;

    const bf16* Asp[3] = {A1, A2, A3};
    const bf16* Bsp[3] = {B1, B2, B3};

    float sum[4][4][4];
    #pragma unroll
    for (int i = 0; i < 4; ++i)
        #pragma unroll
        for (int j = 0; j < 4; ++j)
            #pragma unroll
            for (int q = 0; q < 4; ++q) sum[i][j][q] = 0.0f;

    float accbuf[4][4][4];
    const int nc = K / 32;

    auto load_chunk = [&](int c) {
        const uint32_t sb = sbase + (c % 3) * STG;
        #pragma unroll
        for (int s = 0; s < 3; ++s) {
            const char* Ag = (const char*)Asp[s] + (size_t)m0 * K * 2 + (size_t)c * 64;
            const char* Bg = (const char*)Bsp[s] + (size_t)n0 * K * 2 + (size_t)c * 64;
            #pragma unroll
            for (int p = 0; p < 2; ++p) {
                int idx = tid + p * 256;
                int r = idx >> 2, seg = idx & 3;
                cpasync16(sb + s * TB + r * 80 + seg * 16, Ag + (size_t)r * K * 2 + seg * 16);
                cpasync16(sb + (3 + s) * TB + r * 80 + seg * 16, Bg + (size_t)r * K * 2 + seg * 16);
            }
        }
    };

    load_chunk(0);
    asm volatile("cp.async.commit_group;" ::: "memory");
    if (1 < nc) load_chunk(1);
    asm volatile("cp.async.commit_group;" ::: "memory");

    const int bs_seq6[6] = {1, 1, 2, 0, 0, 0}, as_seq6[6] = {0, 1, 0, 1, 2, 0};

    for (int c = 0; c < nc; ++c) {
        if (c + 2 < nc) load_chunk(c + 2);
        asm volatile("cp.async.commit_group;" ::: "memory");
        asm volatile("cp.async.wait_group 2;" ::: "memory");
        __syncthreads();

        const uint32_t sb = sbase + (c % 3) * STG;
        const bool fresh = ((c & 1) == 0);

        #pragma unroll
        for (int kh = 0; kh < 2; ++kh) {
            uint32_t af[3][4][4];
            #pragma unroll
            for (int s = 0; s < 3; ++s) {
                const uint32_t Ab = sb + s * TB;
                #pragma unroll
                for (int mf = 0; mf < 4; ++mf) {
                    uint32_t r = Ab + (wm * 64 + mf * 16 + lg) * 80 + (kh * 16 + lk) * 2;
                    af[s][mf][0] = lds32(r);
                    af[s][mf][1] = lds32(r + 8 * 80);
                    af[s][mf][2] = lds32(r + 16);
                    af[s][mf][3] = lds32(r + 8 * 80 + 16);
                }
            }
            uint32_t bfr[4][2];
            #pragma unroll
            for (int p = 0; p < 6; ++p) {
                const int bs = bs_seq6[p], as = as_seq6[p];
                const bool reload = (p == 0) || (bs_seq6[p] != bs_seq6[p - 1]);
                if (reload) {
                    const uint32_t Bb = sb + (3 + bs) * TB;
                    #pragma unroll
                    for (int nf = 0; nf < 4; ++nf) {
                        uint32_t r = Bb + (wn * 32 + nf * 8 + lg) * 80 + (kh * 16 + lk) * 2;
                        bfr[nf][0] = lds32(r);
                        bfr[nf][1] = lds32(r + 16);
                    }
                }
                if (fresh && kh == 0 && p == 0) {
                    #pragma unroll
                    for (int mf = 0; mf < 4; ++mf)
                        #pragma unroll
                        for (int nf = 0; nf < 4; ++nf)
                            mma16816_z(accbuf[mf][nf], af[as][mf], bfr[nf]);
                } else {
                    #pragma unroll
                    for (int mf = 0; mf < 4; ++mf)
                        #pragma unroll
                        for (int nf = 0; nf < 4; ++nf)
                            mma16816(accbuf[mf][nf], af[as][mf], bfr[nf]);
                }
            }
        }
        if ((c & 1) == 1 || c == nc - 1) {
            #pragma unroll
            for (int i = 0; i < 4; ++i)
                #pragma unroll
                for (int j = 0; j < 4; ++j)
                    #pragma unroll
                    for (int q = 0; q < 4; ++q)
                        sum[i][j][q] = __fadd_rn(sum[i][j][q], accbuf[i][j][q]);
        }
        __syncthreads();
    }

    // ---- epilogue ----
    #pragma unroll
    for (int mf = 0; mf < 4; ++mf) {
        #pragma unroll
        for (int part = 0; part < 2; ++part) {
            const int row = m0 + wm * 64 + mf * 16 + lg + part * 8;
            #pragma unroll
            for (int nf = 0; nf < 4; ++nf) {
                const int col = n0 + wn * 32 + nf * 8 + lk;
                float f0 = sum[mf][nf][part * 2 + 0] + __ldg(bias + col);
                float f1 = sum[mf][nf][part * 2 + 1] + __ldg(bias + col + 1);
                if (EPI == 0) { f0 = fmaxf(f0, 0.0f); f1 = fmaxf(f1, 0.0f); }
                if (EPI == 1)
                    *(float2*)(outF + (size_t)row * N + col) = make_float2(f0, f1);
                bf16 a1, a2, a3, c1, c2, c3;
                split3(f0, a1, a2, a3);
                split3(f1, c1, c2, c3);
                const size_t o = (size_t)row * N + col;
                *(uint32_t*)(O1 + o) = pack2(a1, c1);
                *(uint32_t*)(O2 + o) = pack2(a2, c2);
                *(uint32_t*)(O3 + o) = pack2(a3, c3);
            }
        }
    }
}

// ============ kernel 2: 64x64-warp-tile 2-split GEMM (scores + decoder, no drain) ============
// CTA 128x128x32, 128 thr, 4 warps (2x2), warp tile 64x64, 2-stage ring, 2 CTAs/SM.
// EPI: 2 score->fp32, 3 sigmoid->splits, 4 none->fp32
template<int EPI>
__global__ void __launch_bounds__(128, 2) gemm64(
    const bf16* __restrict__ A1, const bf16* __restrict__ A2,
    const bf16* __restrict__ B1, const bf16* __restrict__ B2,
    const float* __restrict__ bias, const float* __restrict__ rowterm,
    float* __restrict__ outF, bf16* __restrict__ O1, bf16* __restrict__ O2, bf16* __restrict__ O3,
    int N, int K)
{
    constexpr int TB = 128 * 80;
    constexpr int STG = 4 * TB;
    extern __shared__ char smem[];

    const int tid = threadIdx.x, lane = tid & 31, wid = tid >> 5;
    const int wm = wid >> 1, wn = wid & 1;
    const int m0 = blockIdx.y * 128, n0 = blockIdx.x * 128;
    const uint32_t sbase = smem_u32(smem);
    const int lg = lane >> 2, lk = (lane & 3) * 2;

    const bf16* Asp[2] = {A1, A2};
    const bf16* Bsp[2] = {B1, B2};

    float sum[4][8][4];
    #pragma unroll
    for (int i = 0; i < 4; ++i)
        #pragma unroll
        for (int j = 0; j < 8; ++j)
            #pragma unroll
            for (int q = 0; q < 4; ++q) sum[i][j][q] = 0.0f;

    const int nc = K / 32;

    auto load_chunk = [&](int c) {
        const uint32_t sb = sbase + (c & 1) * STG;
        #pragma unroll
        for (int s = 0; s < 2; ++s) {
            const char* Ag = (const char*)Asp[s] + (size_t)m0 * K * 2 + (size_t)c * 64;
            const char* Bg = (const char*)Bsp[s] + (size_t)n0 * K * 2 + (size_t)c * 64;
            #pragma unroll
            for (int p = 0; p < 4; ++p) {
                int idx = tid + p * 128;
                int r = idx >> 2, seg = idx & 3;
                cpasync16(sb + s * TB + r * 80 + seg * 16, Ag + (size_t)r * K * 2 + seg * 16);
                cpasync16(sb + (2 + s) * TB + r * 80 + seg * 16, Bg + (size_t)r * K * 2 + seg * 16);
            }
        }
    };

    load_chunk(0);
    asm volatile("cp.async.commit_group;" ::: "memory");

    const int bs_seq3[3] = {1, 0, 0}, as_seq3[3] = {0, 1, 0};

    for (int c = 0; c < nc; ++c) {
        if (c + 1 < nc) {
            load_chunk(c + 1);
            asm volatile("cp.async.commit_group;" ::: "memory");
            asm volatile("cp.async.wait_group 1;" ::: "memory");
        } else {
            asm volatile("cp.async.wait_group 0;" ::: "memory");
        }
        __syncthreads();

        const uint32_t sb = sbase + (c & 1) * STG;
        #pragma unroll
        for (int kh = 0; kh < 2; ++kh) {
            uint32_t af[2][4][4];
            #pragma unroll
            for (int s = 0; s < 2; ++s) {
                const uint32_t Ab = sb + s * TB;
                #pragma unroll
                for (int mf = 0; mf < 4; ++mf) {
                    uint32_t r = Ab + (wm * 64 + mf * 16 + lg) * 80 + (kh * 16 + lk) * 2;
                    af[s][mf][0] = lds32(r);
                    af[s][mf][1] = lds32(r + 8 * 80);
                    af[s][mf][2] = lds32(r + 16);
                    af[s][mf][3] = lds32(r + 8 * 80 + 16);
                }
            }
            uint32_t bfr[8][2];
            #pragma unroll
            for (int p = 0; p < 3; ++p) {
                const int bs = bs_seq3[p], as = as_seq3[p];
                const bool reload = (p == 0) || (bs_seq3[p] != bs_seq3[p - 1]);
                if (reload) {
                    const uint32_t Bb = sb + (2 + bs) * TB;
                    #pragma unroll
                    for (int nf = 0; nf < 8; ++nf) {
                        uint32_t r = Bb + (wn * 64 + nf * 8 + lg) * 80 + (kh * 16 + lk) * 2;
                        bfr[nf][0] = lds32(r);
                        bfr[nf][1] = lds32(r + 16);
                    }
                }
                #pragma unroll
                for (int mf = 0; mf < 4; ++mf)
                    #pragma unroll
                    for (int nf = 0; nf < 8; ++nf)
                        mma16816(sum[mf][nf], af[as][mf], bfr[nf]);
            }
        }
        __syncthreads();
    }

    // ---- epilogue ----
    #pragma unroll
    for (int mf = 0; mf < 4; ++mf) {
        #pragma unroll
        for (int part = 0; part < 2; ++part) {
            const int row = m0 + wm * 64 + mf * 16 + lg + part * 8;
            const float rt = (EPI == 2) ? __ldg(rowterm + row) : 0.0f;
            #pragma unroll
            for (int nf = 0; nf < 8; ++nf) {
                const int col = n0 + wn * 64 + nf * 8 + lk;
                const float x0 = sum[mf][nf][part * 2 + 0];
                const float x1 = sum[mf][nf][part * 2 + 1];
                if (EPI == 2) {
                    float t0 = __fadd_rn(rt, __ldg(bias + col));
                    float t1 = __fadd_rn(rt, __ldg(bias + col + 1));
                    *(float2*)(outF + (size_t)row * N + col) =
                        make_float2(__fmaf_rn(-2.0f, x0, t0), __fmaf_rn(-2.0f, x1, t1));
                } else {
                    float f0 = x0 + __ldg(bias + col);
                    float f1 = x1 + __ldg(bias + col + 1);
                    if (EPI == 3) { f0 = 1.0f / (1.0f + expf(-f0)); f1 = 1.0f / (1.0f + expf(-f1)); }
                    if (EPI == 4) {
                        *(float2*)(outF + (size_t)row * N + col) = make_float2(f0, f1);
                    } else {
                        bf16 a1, a2, a3, c1, c2, c3;
                        split3(f0, a1, a2, a3);
                        split3(f1, c1, c2, c3);
                        const size_t o = (size_t)row * N + col;
                        *(uint32_t*)(O1 + o) = pack2(a1, c1);
                        *(uint32_t*)(O2 + o) = pack2(a2, c2);
                        *(uint32_t*)(O3 + o) = pack2(a3, c3);
                    }
                }
            }
        }
    }
}

// ---- elementwise split (n4 = n/4) ----
__global__ void __launch_bounds__(256) split_kernel(
    const float* __restrict__ in, bf16* __restrict__ o1, bf16* __restrict__ o2, bf16* __restrict__ o3, int n4)
{
    int i = blockIdx.x * 256 + threadIdx.x;
    if (i >= n4) return;
    float4 v = ((const float4*)in)[i];
    bf16 a1,a2,a3,b1,b2,b3,c1,c2,c3,d1,d2,d3;
    split3(v.x,a1,a2,a3); split3(v.y,b1,b2,b3); split3(v.z,c1,c2,c3); split3(v.w,d1,d2,d3);
    uint2 u;
    u.x = pack2(a1,b1); u.y = pack2(c1,d1); ((uint2*)o1)[i] = u;
    u.x = pack2(a2,b2); u.y = pack2(c2,d2); ((uint2*)o2)[i] = u;
    u.x = pack2(a3,b3); u.y = pack2(c3,d3); ((uint2*)o3)[i] = u;
}

// ---- W[K,N] -> T[N,K] with split ----
__global__ void __launch_bounds__(256) wsplit_kernel(
    const float* __restrict__ W, bf16* __restrict__ T1, bf16* __restrict__ T2, bf16* __restrict__ T3,
    int K, int N)
{
    __shared__ float t[32][33];
    int tx = threadIdx.x & 31, ty = threadIdx.x >> 5;
    int kb = blockIdx.y * 32, nb = blockIdx.x * 32;
    #pragma unroll
    for (int i = 0; i < 4; ++i)
        t[ty + 8*i][tx] = W[(size_t)(kb + ty + 8*i) * N + nb + tx];
    __syncthreads();
    #pragma unroll
    for (int i = 0; i < 4; ++i) {
        float v = t[tx][ty + 8*i];
        size_t o = (size_t)(nb + ty + 8*i) * K + kb + tx;
        bf16 b1,b2,b3; split3(v,b1,b2,b3);
        T1[o]=b1; T2[o]=b2; T3[o]=b3;
    }
}

__global__ void __launch_bounds__(256) emb2_kernel(const float* __restrict__ emb, float* __restrict__ out)
{
    int warp = (blockIdx.x * 256 + threadIdx.x) >> 5, lane = threadIdx.x & 31;
    if (warp >= KCODES) return;
    const float* e = emb + (size_t)warp * OUT_DIM;
    float s = 0.0f;
    for (int c = lane; c < OUT_DIM; c += 32) s = fmaf(e[c], e[c], s);
    for (int off = 16; off; off >>= 1) s += __shfl_down_sync(0xffffffffu, s, off);
    if (lane == 0) out[warp] = s;
}

__global__ void __launch_bounds__(256) rownorm_kernel(const float* __restrict__ z, float* __restrict__ out)
{
    int row = (blockIdx.x * 256 + threadIdx.x) >> 5, lane = threadIdx.x & 31;
    if (row >= N_ROWS) return;
    const float* zr = z + (size_t)row * OUT_DIM;
    float s = 0.0f;
    for (int c = lane; c < OUT_DIM; c += 32) s = fmaf(zr[c], zr[c], s);
    for (int off = 16; off; off >>= 1) s += __shfl_down_sync(0xffffffffu, s, off);
    if (lane == 0) out[row] = s;
}

// ---- argmin + gather + residual / decoder-input fusion ----
__global__ void __launch_bounds__(256) argmin_kernel(
    const float* __restrict__ scores, const float* __restrict__ ze, const float* __restrict__ emb,
    float* __restrict__ n_out, float* __restrict__ zq_out, float* __restrict__ zenext_out,
    float* __restrict__ rownorm_out, bf16* __restrict__ Z1, bf16* __restrict__ Z2, bf16* __restrict__ Z3,
    const float* __restrict__ decbase)
{
    int row = (blockIdx.x * 256 + threadIdx.x) >> 5, lane = threadIdx.x & 31;
    if (row >= N_ROWS) return;
    const float* s = scores + (size_t)row * KCODES;
    float best = s[lane];
    int bidx = lane;
    #pragma unroll 8
    for (int i = lane + 32; i < KCODES; i += 32) {
        float v = s[i];
        if (v < best) { best = v; bidx = i; }
    }
    #pragma unroll
    for (int off = 16; off; off >>= 1) {
        float v2 = __shfl_down_sync(0xffffffffu, best, off);
        int i2 = __shfl_down_sync(0xffffffffu, bidx, off);
        if (v2 < best || (v2 == best && i2 < bidx)) { best = v2; bidx = i2; }
    }
    bidx = __shfl_sync(0xffffffffu, bidx, 0);
    if (lane == 0) n_out[row] = (float)bidx;

    const float* e = emb + (size_t)bidx * OUT_DIM;
    const float* z = ze + (size_t)row * OUT_DIM;
    float* zq = zq_out + (size_t)row * OUT_DIM;
    const size_t ob = (size_t)row * OUT_DIM;
    if (zenext_out) {
        float* zn = zenext_out + ob;
        float nrm = 0.0f;
        for (int c = lane; c < OUT_DIM; c += 32) {
            float ev = e[c], r = z[c] - ev;
            zq[c] = ev; zn[c] = r;
            bf16 b1,b2,b3; split3(r,b1,b2,b3);
            Z1[ob+c]=b1; Z2[ob+c]=b2; Z3[ob+c]=b3;
            nrm = fmaf(r, r, nrm);
        }
        for (int off = 16; off; off >>= 1) nrm += __shfl_down_sync(0xffffffffu, nrm, off);
        if (lane == 0) rownorm_out[row] = nrm;
    } else {
        const float* db = decbase + ob;
        for (int c = lane; c < OUT_DIM; c += 32) {
            float ev = e[c];
            zq[c] = ev;
            float d = db[c] - (z[c] - ev);   // = zq1+zq2+zq3 up to fp32 rounding
            bf16 b1,b2,b3; split3(d,b1,b2,b3);
            Z1[ob+c]=b1; Z2[ob+c]=b2; Z3[ob+c]=b3;
        }
    }
}

// ---- launch ----
extern "C" void kernel_launch(void* const* d_in, const int* in_sizes, int n_in,
                              void* d_out, int out_size)
{
    const float* x    = (const float*)d_in[0];
    const float* We1  = (const float*)d_in[1];
    const float* be1  = (const float*)d_in[2];
    const float* We2  = (const float*)d_in[3];
    const float* be2  = (const float*)d_in[4];
    const float* Wd1  = (const float*)d_in[5];
    const float* bd1  = (const float*)d_in[6];
    const float* Wd2  = (const float*)d_in[7];
    const float* bd2  = (const float*)d_in[8];
    const float* emb1 = (const float*)d_in[9];
    const float* emb2c= (const float*)d_in[10];
    const float* emb3c= (const float*)d_in[11];

    float* out = (float*)d_out;
    float* recon = out;
    float* ze1 = recon + (size_t)N_ROWS * IN_DIM;
    float* ze2 = ze1 + (size_t)N_ROWS * OUT_DIM;
    float* ze3 = ze2 + (size_t)N_ROWS * OUT_DIM;
    float* zq1 = ze3 + (size_t)N_ROWS * OUT_DIM;
    float* zq2 = zq1 + (size_t)N_ROWS * OUT_DIM;
    float* zq3 = zq2 + (size_t)N_ROWS * OUT_DIM;
    float* n1  = zq3 + (size_t)N_ROWS * OUT_DIM;
    float* n2  = n1 + N_ROWS;
    float* n3  = n2 + N_ROWS;

    bf16 *xs1,*xs2,*xs3,*hs1,*hs2,*hs3,*zs1,*zs2,*zs3;
    bf16 *w1a,*w1b,*w1c,*w2a,*w2b,*w2c,*d1a,*d1b,*d1c,*d2a,*d2b,*d2c,*et1,*et2,*et3;
    float *sc,*e2,*rn;
    cudaGetSymbolAddress((void**)&xs1, g_xs1); cudaGetSymbolAddress((void**)&xs2, g_xs2);
    cudaGetSymbolAddress((void**)&xs3, g_xs3); cudaGetSymbolAddress((void**)&hs1, g_hs1);
    cudaGetSymbolAddress((void**)&hs2, g_hs2); cudaGetSymbolAddress((void**)&hs3, g_hs3);
    cudaGetSymbolAddress((void**)&zs1, g_zs1); cudaGetSymbolAddress((void**)&zs2, g_zs2);
    cudaGetSymbolAddress((void**)&zs3, g_zs3);
    cudaGetSymbolAddress((void**)&w1a, g_w1a); cudaGetSymbolAddress((void**)&w1b, g_w1b);
    cudaGetSymbolAddress((void**)&w1c, g_w1c); cudaGetSymbolAddress((void**)&w2a, g_w2a);
    cudaGetSymbolAddress((void**)&w2b, g_w2b); cudaGetSymbolAddress((void**)&w2c, g_w2c);
    cudaGetSymbolAddress((void**)&d1a, g_d1a); cudaGetSymbolAddress((void**)&d1b, g_d1b);
    cudaGetSymbolAddress((void**)&d1c, g_d1c); cudaGetSymbolAddress((void**)&d2a, g_d2a);
    cudaGetSymbolAddress((void**)&d2b, g_d2b); cudaGetSymbolAddress((void**)&d2c, g_d2c);
    cudaGetSymbolAddress((void**)&et1, g_et1); cudaGetSymbolAddress((void**)&et2, g_et2);
    cudaGetSymbolAddress((void**)&et3, g_et3); cudaGetSymbolAddress((void**)&sc, g_scores);
    cudaGetSymbolAddress((void**)&e2, g_emb2); cudaGetSymbolAddress((void**)&rn, g_rownorm);

    const int SMEME = 3 * (6 * 128 * 80);    // 184320, 3-stage
    const int SMEM64 = 2 * (4 * 128 * 80);   // 81920
    cudaFuncSetAttribute(gemmMMA<0>, cudaFuncAttributeMaxDynamicSharedMemorySize, SMEME);
    cudaFuncSetAttribute(gemmMMA<1>, cudaFuncAttributeMaxDynamicSharedMemorySize, SMEME);
    cudaFuncSetAttribute(gemm64<2>, cudaFuncAttributeMaxDynamicSharedMemorySize, SMEM64);
    cudaFuncSetAttribute(gemm64<3>, cudaFuncAttributeMaxDynamicSharedMemorySize, SMEM64);
    cudaFuncSetAttribute(gemm64<4>, cudaFuncAttributeMaxDynamicSharedMemorySize, SMEM64);

    const dim3 blk(256), dblk(128);
    const int MTILES = N_ROWS / 128;

    // launch index 3 = enc1 GEMM (profiled by ncu capture)
    split_kernel<<<(N_ROWS * IN_DIM / 4 + 255) / 256, blk>>>(x, xs1, xs2, xs3, N_ROWS * IN_DIM / 4);   // 0
    wsplit_kernel<<<dim3(HID / 32, IN_DIM / 32), blk>>>(We1, w1a, w1b, w1c, IN_DIM, HID);              // 1
    wsplit_kernel<<<dim3(OUT_DIM / 32, HID / 32), blk>>>(We2, w2a, w2b, w2c, HID, OUT_DIM);            // 2
    gemmMMA<0><<<dim3(HID / 128, MTILES), blk, SMEME>>>(                                                // 3
        xs1, xs2, xs3, w1a, w1b, w1c, be1, nullptr, hs1, hs2, hs3, HID, IN_DIM);
    gemmMMA<1><<<dim3(OUT_DIM / 128, MTILES), blk, SMEME>>>(
        hs1, hs2, hs3, w2a, w2b, w2c, be2, ze1, zs1, zs2, zs3, OUT_DIM, HID);

    // stage 1 (score GEMM: 64x64-tile, 2-split, no drain)
    rownorm_kernel<<<N_ROWS / 8, blk>>>(ze1, rn);
    split_kernel<<<(KCODES * OUT_DIM / 4 + 255) / 256, blk>>>(emb1, et1, et2, et3, KCODES * OUT_DIM / 4);
    emb2_kernel<<<KCODES / 8, blk>>>(emb1, e2);
    gemm64<2><<<dim3(KCODES / 128, MTILES), dblk, SMEM64>>>(
        zs1, zs2, et1, et2, e2, rn, sc, nullptr, nullptr, nullptr, KCODES, OUT_DIM);
    argmin_kernel<<<N_ROWS / 8, blk>>>(sc, ze1, emb1, n1, zq1, ze2, rn, zs1, zs2, zs3, nullptr);

    // stage 2
    split_kernel<<<(KCODES * OUT_DIM / 4 + 255) / 256, blk>>>(emb2c, et1, et2, et3, KCODES * OUT_DIM / 4);
    emb2_kernel<<<KCODES / 8, blk>>>(emb2c, e2);
    gemm64<2><<<dim3(KCODES / 128, MTILES), dblk, SMEM64>>>(
        zs1, zs2, et1, et2, e2, rn, sc, nullptr, nullptr, nullptr, KCODES, OUT_DIM);
    argmin_kernel<<<N_ROWS / 8, blk>>>(sc, ze2, emb2c, n2, zq2, ze3, rn, zs1, zs2, zs3, nullptr);

    // stage 3 (fused: emits decoder-input splits = zq1+zq2+zq3 via ze1 - r3)
    split_kernel<<<(KCODES * OUT_DIM / 4 + 255) / 256, blk>>>(emb3c, et1, et2, et3, KCODES * OUT_DIM / 4);
    emb2_kernel<<<KCODES / 8, blk>>>(emb3c, e2);
    gemm64<2><<<dim3(KCODES / 128, MTILES), dblk, SMEM64>>>(
        zs1, zs2, et1, et2, e2, rn, sc, nullptr, nullptr, nullptr, KCODES, OUT_DIM);
    argmin_kernel<<<N_ROWS / 8, blk>>>(sc, ze3, emb3c, n3, zq3, nullptr, nullptr, zs1, zs2, zs3, ze1);

    // decoder (64x64-tile 2-split GEMMs)
    wsplit_kernel<<<dim3(HID / 32, OUT_DIM / 32), blk>>>(Wd1, d1a, d1b, d1c, OUT_DIM, HID);
    gemm64<3><<<dim3(HID / 128, MTILES), dblk, SMEM64>>>(
        zs1, zs2, d1a, d1b, bd1, nullptr, nullptr, hs1, hs2, hs3, HID, OUT_DIM);
    wsplit_kernel<<<dim3(IN_DIM / 32, HID / 32), blk>>>(Wd2, d2a, d2b, d2c, HID, IN_DIM);
    gemm64<4><<<dim3(IN_DIM / 128, MTILES), dblk, SMEM64>>>(
        hs1, hs2, d2a, d2b, bd2, nullptr, recon, nullptr, nullptr, nullptr, IN_DIM, HID);
}

// round 16
// speedup vs baseline: 1.0546x; 1.0546x over previous
#include <cuda_runtime.h>
#include <cuda_bf16.h>
#include <math.h>
#include <stdint.h>

#define N_ROWS 32768
#define IN_DIM 768
#define HID 2048
#define OUT_DIM 256
#define KCODES 1024

typedef __nv_bfloat16 bf16;

// ---- scratch (device globals) ----
__device__ bf16 g_xs1[(size_t)N_ROWS * IN_DIM], g_xs2[(size_t)N_ROWS * IN_DIM], g_xs3[(size_t)N_ROWS * IN_DIM];
__device__ bf16 g_hs1[(size_t)N_ROWS * HID], g_hs2[(size_t)N_ROWS * HID], g_hs3[(size_t)N_ROWS * HID];
__device__ bf16 g_zs1[(size_t)N_ROWS * OUT_DIM], g_zs2[(size_t)N_ROWS * OUT_DIM], g_zs3[(size_t)N_ROWS * OUT_DIM];
__device__ bf16 g_w1a[(size_t)HID * IN_DIM], g_w1b[(size_t)HID * IN_DIM], g_w1c[(size_t)HID * IN_DIM];
__device__ bf16 g_w2a[(size_t)OUT_DIM * HID], g_w2b[(size_t)OUT_DIM * HID], g_w2c[(size_t)OUT_DIM * HID];
__device__ bf16 g_d1a[(size_t)HID * OUT_DIM], g_d1b[(size_t)HID * OUT_DIM], g_d1c[(size_t)HID * OUT_DIM];
__device__ bf16 g_d2a[(size_t)IN_DIM * HID], g_d2b[(size_t)IN_DIM * HID], g_d2c[(size_t)IN_DIM * HID];
__device__ bf16 g_et1[KCODES * OUT_DIM], g_et2[KCODES * OUT_DIM], g_et3[KCODES * OUT_DIM];
__device__ float2 g_part[(size_t)N_ROWS * (KCODES / 128)];   // per-row per-codeblock (min, idx)
__device__ float g_emb2[KCODES];
__device__ float g_rownorm[N_ROWS];

// ---- helpers ----
__device__ __forceinline__ uint32_t smem_u32(const void* p) {
    uint32_t a;
    asm("{ .reg .u64 t; cvta.to.shared.u64 t, %1; cvt.u32.u64 %0, t; }" : "=r"(a) : "l"(p));
    return a;
}
__device__ __forceinline__ uint32_t lds32(uint32_t a) {
    uint32_t v; asm volatile("ld.shared.b32 %0, [%1];" : "=r"(v) : "r"(a)); return v;
}
__device__ __forceinline__ void cpasync16(uint32_t s, const void* g) {
    asm volatile("cp.async.cg.shared.global [%0], [%1], 16;" :: "r"(s), "l"(g));
}
__device__ __forceinline__ void mma16816(float* d, const uint32_t* a, const uint32_t* b) {
    asm volatile(
        "mma.sync.aligned.m16n8k16.row.col.f32.bf16.bf16.f32 "
        "{%0,%1,%2,%3}, {%4,%5,%6,%7}, {%8,%9}, {%0,%1,%2,%3};"
        : "+f"(d[0]), "+f"(d[1]), "+f"(d[2]), "+f"(d[3])
        : "r"(a[0]), "r"(a[1]), "r"(a[2]), "r"(a[3]), "r"(b[0]), "r"(b[1]));
}
__device__ __forceinline__ void split3(float v, bf16& b1, bf16& b2, bf16& b3) {
    b1 = __float2bfloat16(v);
    float r = v - __bfloat162float(b1);
    b2 = __float2bfloat16(r);
    b3 = __float2bfloat16(r - __bfloat162float(b2));
}
__device__ __forceinline__ uint32_t pack2(bf16 a, bf16 b) {
    return (uint32_t)__nv_bfloat16_raw(a).x | ((uint32_t)__nv_bfloat16_raw(b).x << 16);
}

// ============ kernel 1: encoder GEMM (NP=6, 64x32 warp tile, per-chunk drain) ============
// R12 configuration (best measured). Tile 128x128x32, 256 thr, 8 warps (2x4), 3-stage ring.
// EPI: 0 relu->splits, 1 none->fp32+splits
template<int EPI>
__global__ void __launch_bounds__(256, 1) gemmMMA(
    const bf16* __restrict__ A1, const bf16* __restrict__ A2, const bf16* __restrict__ A3,
    const bf16* __restrict__ B1, const bf16* __restrict__ B2, const bf16* __restrict__ B3,
    const float* __restrict__ bias,
    float* __restrict__ outF, bf16* __restrict__ O1, bf16* __restrict__ O2, bf16* __restrict__ O3,
    int N, int K)
{
    constexpr int TB = 128 * 80;
    constexpr int STG = 6 * TB;
    extern __shared__ char smem[];

    const int tid = threadIdx.x, lane = tid & 31, wid = tid >> 5;
    const int wm = wid >> 2, wn = wid & 3;
    const int m0 = blockIdx.y * 128, n0 = blockIdx.x * 128;
    const uint32_t sbase = smem_u32(smem);
    const int lg = lane >> 2, lk = (lane & 3) * 2;

    const bf16* Asp[3] = {A1, A2, A3};
    const bf16* Bsp[3] = {B1, B2, B3};

    float sum[4][4][4];
    #pragma unroll
    for (int i = 0; i < 4; ++i)
        #pragma unroll
        for (int j = 0; j < 4; ++j)
            #pragma unroll
            for (int q = 0; q < 4; ++q) sum[i][j][q] = 0.0f;

    const int nc = K / 32;

    auto load_chunk = [&](int c) {
        const uint32_t sb = sbase + (c % 3) * STG;
        #pragma unroll
        for (int s = 0; s < 3; ++s) {
            const char* Ag = (const char*)Asp[s] + (size_t)m0 * K * 2 + (size_t)c * 64;
            const char* Bg = (const char*)Bsp[s] + (size_t)n0 * K * 2 + (size_t)c * 64;
            #pragma unroll
            for (int p = 0; p < 2; ++p) {
                int idx = tid + p * 256;
                int r = idx >> 2, seg = idx & 3;
                cpasync16(sb + s * TB + r * 80 + seg * 16, Ag + (size_t)r * K * 2 + seg * 16);
                cpasync16(sb + (3 + s) * TB + r * 80 + seg * 16, Bg + (size_t)r * K * 2 + seg * 16);
            }
        }
    };

    load_chunk(0);
    asm volatile("cp.async.commit_group;" ::: "memory");
    if (1 < nc) load_chunk(1);
    asm volatile("cp.async.commit_group;" ::: "memory");

    const int bs_seq6[6] = {1, 1, 2, 0, 0, 0}, as_seq6[6] = {0, 1, 0, 1, 2, 0};

    for (int c = 0; c < nc; ++c) {
        if (c + 2 < nc) load_chunk(c + 2);
        asm volatile("cp.async.commit_group;" ::: "memory");
        asm volatile("cp.async.wait_group 2;" ::: "memory");
        __syncthreads();

        const uint32_t sb = sbase + (c % 3) * STG;

        float accbuf[4][4][4];
        #pragma unroll
        for (int i = 0; i < 4; ++i)
            #pragma unroll
            for (int j = 0; j < 4; ++j)
                #pragma unroll
                for (int q = 0; q < 4; ++q) accbuf[i][j][q] = 0.0f;

        #pragma unroll
        for (int kh = 0; kh < 2; ++kh) {
            uint32_t af[3][4][4];
            #pragma unroll
            for (int s = 0; s < 3; ++s) {
                const uint32_t Ab = sb + s * TB;
                #pragma unroll
                for (int mf = 0; mf < 4; ++mf) {
                    uint32_t r = Ab + (wm * 64 + mf * 16 + lg) * 80 + (kh * 16 + lk) * 2;
                    af[s][mf][0] = lds32(r);
                    af[s][mf][1] = lds32(r + 8 * 80);
                    af[s][mf][2] = lds32(r + 16);
                    af[s][mf][3] = lds32(r + 8 * 80 + 16);
                }
            }
            uint32_t bfr[4][2];
            #pragma unroll
            for (int p = 0; p < 6; ++p) {
                const int bs = bs_seq6[p], as = as_seq6[p];
                const bool reload = (p == 0) || (bs_seq6[p] != bs_seq6[p - 1]);
                if (reload) {
                    const uint32_t Bb = sb + (3 + bs) * TB;
                    #pragma unroll
                    for (int nf = 0; nf < 4; ++nf) {
                        uint32_t r = Bb + (wn * 32 + nf * 8 + lg) * 80 + (kh * 16 + lk) * 2;
                        bfr[nf][0] = lds32(r);
                        bfr[nf][1] = lds32(r + 16);
                    }
                }
                #pragma unroll
                for (int mf = 0; mf < 4; ++mf)
                    #pragma unroll
                    for (int nf = 0; nf < 4; ++nf)
                        mma16816(accbuf[mf][nf], af[as][mf], bfr[nf]);
            }
        }
        #pragma unroll
        for (int i = 0; i < 4; ++i)
            #pragma unroll
            for (int j = 0; j < 4; ++j)
                #pragma unroll
                for (int q = 0; q < 4; ++q)
                    sum[i][j][q] = __fadd_rn(sum[i][j][q], accbuf[i][j][q]);
        __syncthreads();
    }

    // ---- epilogue ----
    #pragma unroll
    for (int mf = 0; mf < 4; ++mf) {
        #pragma unroll
        for (int part = 0; part < 2; ++part) {
            const int row = m0 + wm * 64 + mf * 16 + lg + part * 8;
            #pragma unroll
            for (int nf = 0; nf < 4; ++nf) {
                const int col = n0 + wn * 32 + nf * 8 + lk;
                float f0 = sum[mf][nf][part * 2 + 0] + __ldg(bias + col);
                float f1 = sum[mf][nf][part * 2 + 1] + __ldg(bias + col + 1);
                if (EPI == 0) { f0 = fmaxf(f0, 0.0f); f1 = fmaxf(f1, 0.0f); }
                if (EPI == 1)
                    *(float2*)(outF + (size_t)row * N + col) = make_float2(f0, f1);
                bf16 a1, a2, a3, c1, c2, c3;
                split3(f0, a1, a2, a3);
                split3(f1, c1, c2, c3);
                const size_t o = (size_t)row * N + col;
                *(uint32_t*)(O1 + o) = pack2(a1, c1);
                *(uint32_t*)(O2 + o) = pack2(a2, c2);
                *(uint32_t*)(O3 + o) = pack2(a3, c3);
            }
        }
    }
}

// ============ kernel 2: 64x64-warp-tile 2-split GEMM (scores + decoder, no drain) ============
// CTA 128x128x32, 128 thr, 4 warps (2x2), warp tile 64x64, 2-stage ring, 2 CTAs/SM.
// EPI: 2 score->fused partial argmin (no score matrix!), 3 sigmoid->splits, 4 none->fp32
template<int EPI>
__global__ void __launch_bounds__(128, 2) gemm64(
    const bf16* __restrict__ A1, const bf16* __restrict__ A2,
    const bf16* __restrict__ B1, const bf16* __restrict__ B2,
    const float* __restrict__ bias, const float* __restrict__ rowterm,
    float* __restrict__ outF, bf16* __restrict__ O1, bf16* __restrict__ O2, bf16* __restrict__ O3,
    float2* __restrict__ partOut,
    int N, int K)
{
    constexpr int TB = 128 * 80;
    constexpr int STG = 4 * TB;
    extern __shared__ char smem[];

    const int tid = threadIdx.x, lane = tid & 31, wid = tid >> 5;
    const int wm = wid >> 1, wn = wid & 1;
    const int m0 = blockIdx.y * 128, n0 = blockIdx.x * 128;
    const uint32_t sbase = smem_u32(smem);
    const int lg = lane >> 2, lk = (lane & 3) * 2;

    const bf16* Asp[2] = {A1, A2};
    const bf16* Bsp[2] = {B1, B2};

    float sum[4][8][4];
    #pragma unroll
    for (int i = 0; i < 4; ++i)
        #pragma unroll
        for (int j = 0; j < 8; ++j)
            #pragma unroll
            for (int q = 0; q < 4; ++q) sum[i][j][q] = 0.0f;

    const int nc = K / 32;

    auto load_chunk = [&](int c) {
        const uint32_t sb = sbase + (c & 1) * STG;
        #pragma unroll
        for (int s = 0; s < 2; ++s) {
            const char* Ag = (const char*)Asp[s] + (size_t)m0 * K * 2 + (size_t)c * 64;
            const char* Bg = (const char*)Bsp[s] + (size_t)n0 * K * 2 + (size_t)c * 64;
            #pragma unroll
            for (int p = 0; p < 4; ++p) {
                int idx = tid + p * 128;
                int r = idx >> 2, seg = idx & 3;
                cpasync16(sb + s * TB + r * 80 + seg * 16, Ag + (size_t)r * K * 2 + seg * 16);
                cpasync16(sb + (2 + s) * TB + r * 80 + seg * 16, Bg + (size_t)r * K * 2 + seg * 16);
            }
        }
    };

    load_chunk(0);
    asm volatile("cp.async.commit_group;" ::: "memory");

    const int bs_seq3[3] = {1, 0, 0}, as_seq3[3] = {0, 1, 0};

    for (int c = 0; c < nc; ++c) {
        if (c + 1 < nc) {
            load_chunk(c + 1);
            asm volatile("cp.async.commit_group;" ::: "memory");
            asm volatile("cp.async.wait_group 1;" ::: "memory");
        } else {
            asm volatile("cp.async.wait_group 0;" ::: "memory");
        }
        __syncthreads();

        const uint32_t sb = sbase + (c & 1) * STG;
        #pragma unroll
        for (int kh = 0; kh < 2; ++kh) {
            uint32_t af[2][4][4];
            #pragma unroll
            for (int s = 0; s < 2; ++s) {
                const uint32_t Ab = sb + s * TB;
                #pragma unroll
                for (int mf = 0; mf < 4; ++mf) {
                    uint32_t r = Ab + (wm * 64 + mf * 16 + lg) * 80 + (kh * 16 + lk) * 2;
                    af[s][mf][0] = lds32(r);
                    af[s][mf][1] = lds32(r + 8 * 80);
                    af[s][mf][2] = lds32(r + 16);
                    af[s][mf][3] = lds32(r + 8 * 80 + 16);
                }
            }
            uint32_t bfr[8][2];
            #pragma unroll
            for (int p = 0; p < 3; ++p) {
                const int bs = bs_seq3[p], as = as_seq3[p];
                const bool reload = (p == 0) || (bs_seq3[p] != bs_seq3[p - 1]);
                if (reload) {
                    const uint32_t Bb = sb + (2 + bs) * TB;
                    #pragma unroll
                    for (int nf = 0; nf < 8; ++nf) {
                        uint32_t r = Bb + (wn * 64 + nf * 8 + lg) * 80 + (kh * 16 + lk) * 2;
                        bfr[nf][0] = lds32(r);
                        bfr[nf][1] = lds32(r + 16);
                    }
                }
                #pragma unroll
                for (int mf = 0; mf < 4; ++mf)
                    #pragma unroll
                    for (int nf = 0; nf < 8; ++nf)
                        mma16816(sum[mf][nf], af[as][mf], bfr[nf]);
            }
        }
        __syncthreads();
    }

    // ---- epilogue ----
    if (EPI == 2) {
        // fused partial argmin: per row, min over this CTA's 128 codes.
        float2* spart = (float2*)smem;   // [2 wn][128 rows], ring buffers done
        #pragma unroll
        for (int mf = 0; mf < 4; ++mf) {
            #pragma unroll
            for (int part = 0; part < 2; ++part) {
                const int lrow = wm * 64 + mf * 16 + lg + part * 8;
                const float rt = __ldg(rowterm + m0 + lrow);
                float best = 3.4e38f;
                int bidx = 0;
                #pragma unroll
                for (int nf = 0; nf < 8; ++nf) {
                    const int col = n0 + wn * 64 + nf * 8 + lk;
                    float t0 = __fadd_rn(rt, __ldg(bias + col));
                    float t1 = __fadd_rn(rt, __ldg(bias + col + 1));
                    float d0 = __fmaf_rn(-2.0f, sum[mf][nf][part * 2 + 0], t0);
                    float d1 = __fmaf_rn(-2.0f, sum[mf][nf][part * 2 + 1], t1);
                    if (d0 < best) { best = d0; bidx = col; }
                    if (d1 < best) { best = d1; bidx = col + 1; }
                }
                // reduce across the 4 lanes holding this row (lane bits 0-1)
                #pragma unroll
                for (int off = 1; off <= 2; off <<= 1) {
                    float v2 = __shfl_xor_sync(0xffffffffu, best, off);
                    int i2 = __shfl_xor_sync(0xffffffffu, bidx, off);
                    if (v2 < best || (v2 == best && i2 < bidx)) { best = v2; bidx = i2; }
                }
                if ((lane & 3) == 0)
                    spart[wn * 128 + lrow] = make_float2(best, (float)bidx);
            }
        }
        __syncthreads();
        // combine the two warp-halves, one thread per row
        if (tid < 128) {
            float2 a = spart[tid], b = spart[128 + tid];
            float2 w = (b.x < a.x || (b.x == a.x && b.y < a.y)) ? b : a;
            partOut[(size_t)(m0 + tid) * (KCODES / 128) + blockIdx.x] = w;
        }
        return;
    }
    #pragma unroll
    for (int mf = 0; mf < 4; ++mf) {
        #pragma unroll
        for (int part = 0; part < 2; ++part) {
            const int row = m0 + wm * 64 + mf * 16 + lg + part * 8;
            #pragma unroll
            for (int nf = 0; nf < 8; ++nf) {
                const int col = n0 + wn * 64 + nf * 8 + lk;
                float f0 = sum[mf][nf][part * 2 + 0] + __ldg(bias + col);
                float f1 = sum[mf][nf][part * 2 + 1] + __ldg(bias + col + 1);
                if (EPI == 3) { f0 = 1.0f / (1.0f + expf(-f0)); f1 = 1.0f / (1.0f + expf(-f1)); }
                if (EPI == 4) {
                    *(float2*)(outF + (size_t)row * N + col) = make_float2(f0, f1);
                } else {
                    bf16 a1, a2, a3, c1, c2, c3;
                    split3(f0, a1, a2, a3);
                    split3(f1, c1, c2, c3);
                    const size_t o = (size_t)row * N + col;
                    *(uint32_t*)(O1 + o) = pack2(a1, c1);
                    *(uint32_t*)(O2 + o) = pack2(a2, c2);
                    *(uint32_t*)(O3 + o) = pack2(a3, c3);
                }
            }
        }
    }
}

// ---- elementwise split (n4 = n/4) ----
__global__ void __launch_bounds__(256) split_kernel(
    const float* __restrict__ in, bf16* __restrict__ o1, bf16* __restrict__ o2, bf16* __restrict__ o3, int n4)
{
    int i = blockIdx.x * 256 + threadIdx.x;
    if (i >= n4) return;
    float4 v = ((const float4*)in)[i];
    bf16 a1,a2,a3,b1,b2,b3,c1,c2,c3,d1,d2,d3;
    split3(v.x,a1,a2,a3); split3(v.y,b1,b2,b3); split3(v.z,c1,c2,c3); split3(v.w,d1,d2,d3);
    uint2 u;
    u.x = pack2(a1,b1); u.y = pack2(c1,d1); ((uint2*)o1)[i] = u;
    u.x = pack2(a2,b2); u.y = pack2(c2,d2); ((uint2*)o2)[i] = u;
    u.x = pack2(a3,b3); u.y = pack2(c3,d3); ((uint2*)o3)[i] = u;
}

// ---- W[K,N] -> T[N,K] with split ----
__global__ void __launch_bounds__(256) wsplit_kernel(
    const float* __restrict__ W, bf16* __restrict__ T1, bf16* __restrict__ T2, bf16* __restrict__ T3,
    int K, int N)
{
    __shared__ float t[32][33];
    int tx = threadIdx.x & 31, ty = threadIdx.x >> 5;
    int kb = blockIdx.y * 32, nb = blockIdx.x * 32;
    #pragma unroll
    for (int i = 0; i < 4; ++i)
        t[ty + 8*i][tx] = W[(size_t)(kb + ty + 8*i) * N + nb + tx];
    __syncthreads();
    #pragma unroll
    for (int i = 0; i < 4; ++i) {
        float v = t[tx][ty + 8*i];
        size_t o = (size_t)(nb + ty + 8*i) * K + kb + tx;
        bf16 b1,b2,b3; split3(v,b1,b2,b3);
        T1[o]=b1; T2[o]=b2; T3[o]=b3;
    }
}

__global__ void __launch_bounds__(256) emb2_kernel(const float* __restrict__ emb, float* __restrict__ out)
{
    int warp = (blockIdx.x * 256 + threadIdx.x) >> 5, lane = threadIdx.x & 31;
    if (warp >= KCODES) return;
    const float* e = emb + (size_t)warp * OUT_DIM;
    float s = 0.0f;
    for (int c = lane; c < OUT_DIM; c += 32) s = fmaf(e[c], e[c], s);
    for (int off = 16; off; off >>= 1) s += __shfl_down_sync(0xffffffffu, s, off);
    if (lane == 0) out[warp] = s;
}

__global__ void __launch_bounds__(256) rownorm_kernel(const float* __restrict__ z, float* __restrict__ out)
{
    int row = (blockIdx.x * 256 + threadIdx.x) >> 5, lane = threadIdx.x & 31;
    if (row >= N_ROWS) return;
    const float* zr = z + (size_t)row * OUT_DIM;
    float s = 0.0f;
    for (int c = lane; c < OUT_DIM; c += 32) s = fmaf(zr[c], zr[c], s);
    for (int off = 16; off; off >>= 1) s += __shfl_down_sync(0xffffffffu, s, off);
    if (lane == 0) out[row] = s;
}

// ---- final argmin over 8 partials + gather + residual / decoder-input fusion ----
__global__ void __launch_bounds__(256) argmin_kernel(
    const float2* __restrict__ part, const float* __restrict__ ze, const float* __restrict__ emb,
    float* __restrict__ n_out, float* __restrict__ zq_out, float* __restrict__ zenext_out,
    float* __restrict__ rownorm_out, bf16* __restrict__ Z1, bf16* __restrict__ Z2, bf16* __restrict__ Z3,
    const float* __restrict__ decbase)
{
    int row = (blockIdx.x * 256 + threadIdx.x) >> 5, lane = threadIdx.x & 31;
    if (row >= N_ROWS) return;

    float best = 3.4e38f;
    int bidx = KCODES;
    if (lane < (KCODES / 128)) {
        float2 p = part[(size_t)row * (KCODES / 128) + lane];
        best = p.x;
        bidx = (int)p.y;
    }
    #pragma unroll
    for (int off = 4; off; off >>= 1) {
        float v2 = __shfl_down_sync(0xffffffffu, best, off);
        int i2 = __shfl_down_sync(0xffffffffu, bidx, off);
        if (v2 < best || (v2 == best && i2 < bidx)) { best = v2; bidx = i2; }
    }
    bidx = __shfl_sync(0xffffffffu, bidx, 0);
    if (lane == 0) n_out[row] = (float)bidx;

    const float* e = emb + (size_t)bidx * OUT_DIM;
    const float* z = ze + (size_t)row * OUT_DIM;
    float* zq = zq_out + (size_t)row * OUT_DIM;
    const size_t ob = (size_t)row * OUT_DIM;
    if (zenext_out) {
        float* zn = zenext_out + ob;
        float nrm = 0.0f;
        for (int c = lane; c < OUT_DIM; c += 32) {
            float ev = e[c], r = z[c] - ev;
            zq[c] = ev; zn[c] = r;
            bf16 b1,b2,b3; split3(r,b1,b2,b3);
            Z1[ob+c]=b1; Z2[ob+c]=b2; Z3[ob+c]=b3;
            nrm = fmaf(r, r, nrm);
        }
        for (int off = 16; off; off >>= 1) nrm += __shfl_down_sync(0xffffffffu, nrm, off);
        if (lane == 0) rownorm_out[row] = nrm;
    } else {
        const float* db = decbase + ob;
        for (int c = lane; c < OUT_DIM; c += 32) {
            float ev = e[c];
            zq[c] = ev;
            float d = db[c] - (z[c] - ev);   // = zq1+zq2+zq3 up to fp32 rounding
            bf16 b1,b2,b3; split3(d,b1,b2,b3);
            Z1[ob+c]=b1; Z2[ob+c]=b2; Z3[ob+c]=b3;
        }
    }
}

// ---- launch ----
extern "C" void kernel_launch(void* const* d_in, const int* in_sizes, int n_in,
                              void* d_out, int out_size)
{
    const float* x    = (const float*)d_in[0];
    const float* We1  = (const float*)d_in[1];
    const float* be1  = (const float*)d_in[2];
    const float* We2  = (const float*)d_in[3];
    const float* be2  = (const float*)d_in[4];
    const float* Wd1  = (const float*)d_in[5];
    const float* bd1  = (const float*)d_in[6];
    const float* Wd2  = (const float*)d_in[7];
    const float* bd2  = (const float*)d_in[8];
    const float* emb1 = (const float*)d_in[9];
    const float* emb2c= (const float*)d_in[10];
    const float* emb3c= (const float*)d_in[11];

    float* out = (float*)d_out;
    float* recon = out;
    float* ze1 = recon + (size_t)N_ROWS * IN_DIM;
    float* ze2 = ze1 + (size_t)N_ROWS * OUT_DIM;
    float* ze3 = ze2 + (size_t)N_ROWS * OUT_DIM;
    float* zq1 = ze3 + (size_t)N_ROWS * OUT_DIM;
    float* zq2 = zq1 + (size_t)N_ROWS * OUT_DIM;
    float* zq3 = zq2 + (size_t)N_ROWS * OUT_DIM;
    float* n1  = zq3 + (size_t)N_ROWS * OUT_DIM;
    float* n2  = n1 + N_ROWS;
    float* n3  = n2 + N_ROWS;

    bf16 *xs1,*xs2,*xs3,*hs1,*hs2,*hs3,*zs1,*zs2,*zs3;
    bf16 *w1a,*w1b,*w1c,*w2a,*w2b,*w2c,*d1a,*d1b,*d1c,*d2a,*d2b,*d2c,*et1,*et2,*et3;
    float *e2,*rn;
    float2 *pt;
    cudaGetSymbolAddress((void**)&xs1, g_xs1); cudaGetSymbolAddress((void**)&xs2, g_xs2);
    cudaGetSymbolAddress((void**)&xs3, g_xs3); cudaGetSymbolAddress((void**)&hs1, g_hs1);
    cudaGetSymbolAddress((void**)&hs2, g_hs2); cudaGetSymbolAddress((void**)&hs3, g_hs3);
    cudaGetSymbolAddress((void**)&zs1, g_zs1); cudaGetSymbolAddress((void**)&zs2, g_zs2);
    cudaGetSymbolAddress((void**)&zs3, g_zs3);
    cudaGetSymbolAddress((void**)&w1a, g_w1a); cudaGetSymbolAddress((void**)&w1b, g_w1b);
    cudaGetSymbolAddress((void**)&w1c, g_w1c); cudaGetSymbolAddress((void**)&w2a, g_w2a);
    cudaGetSymbolAddress((void**)&w2b, g_w2b); cudaGetSymbolAddress((void**)&w2c, g_w2c);
    cudaGetSymbolAddress((void**)&d1a, g_d1a); cudaGetSymbolAddress((void**)&d1b, g_d1b);
    cudaGetSymbolAddress((void**)&d1c, g_d1c); cudaGetSymbolAddress((void**)&d2a, g_d2a);
    cudaGetSymbolAddress((void**)&d2b, g_d2b); cudaGetSymbolAddress((void**)&d2c, g_d2c);
    cudaGetSymbolAddress((void**)&et1, g_et1); cudaGetSymbolAddress((void**)&et2, g_et2);
    cudaGetSymbolAddress((void**)&et3, g_et3); cudaGetSymbolAddress((void**)&pt, g_part);
    cudaGetSymbolAddress((void**)&e2, g_emb2); cudaGetSymbolAddress((void**)&rn, g_rownorm);

    const int SMEME = 3 * (6 * 128 * 80);    // 184320
    const int SMEM64 = 2 * (4 * 128 * 80);   // 81920
    cudaFuncSetAttribute(gemmMMA<0>, cudaFuncAttributeMaxDynamicSharedMemorySize, SMEME);
    cudaFuncSetAttribute(gemmMMA<1>, cudaFuncAttributeMaxDynamicSharedMemorySize, SMEME);
    cudaFuncSetAttribute(gemm64<2>, cudaFuncAttributeMaxDynamicSharedMemorySize, SMEM64);
    cudaFuncSetAttribute(gemm64<3>, cudaFuncAttributeMaxDynamicSharedMemorySize, SMEM64);
    cudaFuncSetAttribute(gemm64<4>, cudaFuncAttributeMaxDynamicSharedMemorySize, SMEM64);

    const dim3 blk(256), dblk(128);
    const int MTILES = N_ROWS / 128;

    // launch index 3 = enc1 GEMM (profiled by ncu capture)
    split_kernel<<<(N_ROWS * IN_DIM / 4 + 255) / 256, blk>>>(x, xs1, xs2, xs3, N_ROWS * IN_DIM / 4);   // 0
    wsplit_kernel<<<dim3(HID / 32, IN_DIM / 32), blk>>>(We1, w1a, w1b, w1c, IN_DIM, HID);              // 1
    wsplit_kernel<<<dim3(OUT_DIM / 32, HID / 32), blk>>>(We2, w2a, w2b, w2c, HID, OUT_DIM);            // 2
    gemmMMA<0><<<dim3(HID / 128, MTILES), blk, SMEME>>>(                                                // 3
        xs1, xs2, xs3, w1a, w1b, w1c, be1, nullptr, hs1, hs2, hs3, HID, IN_DIM);
    gemmMMA<1><<<dim3(OUT_DIM / 128, MTILES), blk, SMEME>>>(
        hs1, hs2, hs3, w2a, w2b, w2c, be2, ze1, zs1, zs2, zs3, OUT_DIM, HID);

    // stage 1 (score GEMM with fused partial argmin)
    rownorm_kernel<<<N_ROWS / 8, blk>>>(ze1, rn);
    split_kernel<<<(KCODES * OUT_DIM / 4 + 255) / 256, blk>>>(emb1, et1, et2, et3, KCODES * OUT_DIM / 4);
    emb2_kernel<<<KCODES / 8, blk>>>(emb1, e2);
    gemm64<2><<<dim3(KCODES / 128, MTILES), dblk, SMEM64>>>(
        zs1, zs2, et1, et2, e2, rn, nullptr, nullptr, nullptr, nullptr, pt, KCODES, OUT_DIM);
    argmin_kernel<<<N_ROWS / 8, blk>>>(pt, ze1, emb1, n1, zq1, ze2, rn, zs1, zs2, zs3, nullptr);

    // stage 2
    split_kernel<<<(KCODES * OUT_DIM / 4 + 255) / 256, blk>>>(emb2c, et1, et2, et3, KCODES * OUT_DIM / 4);
    emb2_kernel<<<KCODES / 8, blk>>>(emb2c, e2);
    gemm64<2><<<dim3(KCODES / 128, MTILES), dblk, SMEM64>>>(
        zs1, zs2, et1, et2, e2, rn, nullptr, nullptr, nullptr, nullptr, pt, KCODES, OUT_DIM);
    argmin_kernel<<<N_ROWS / 8, blk>>>(pt, ze2, emb2c, n2, zq2, ze3, rn, zs1, zs2, zs3, nullptr);

    // stage 3 (fused: emits decoder-input splits = zq1+zq2+zq3 via ze1 - r3)
    split_kernel<<<(KCODES * OUT_DIM / 4 + 255) / 256, blk>>>(emb3c, et1, et2, et3, KCODES * OUT_DIM / 4);
    emb2_kernel<<<KCODES / 8, blk>>>(emb3c, e2);
    gemm64<2><<<dim3(KCODES / 128, MTILES), dblk, SMEM64>>>(
        zs1, zs2, et1, et2, e2, rn, nullptr, nullptr, nullptr, nullptr, pt, KCODES, OUT_DIM);
    argmin_kernel<<<N_ROWS / 8, blk>>>(pt, ze3, emb3c, n3, zq3, nullptr, nullptr, zs1, zs2, zs3, ze1);

    // decoder (64x64-tile 2-split GEMMs)
    wsplit_kernel<<<dim3(HID / 32, OUT_DIM / 32), blk>>>(Wd1, d1a, d1b, d1c, OUT_DIM, HID);
    gemm64<3><<<dim3(HID / 128, MTILES), dblk, SMEM64>>>(
        zs1, zs2, d1a, d1b, bd1, nullptr, nullptr, hs1, hs2, hs3, nullptr, HID, OUT_DIM);
    wsplit_kernel<<<dim3(IN_DIM / 32, HID / 32), blk>>>(Wd2, d2a, d2b, d2c, HID, IN_DIM);
    gemm64<4><<<dim3(IN_DIM / 128, MTILES), dblk, SMEM64>>>(
        hs1, hs2, d2a, d2b, bd2, nullptr, recon, nullptr, nullptr, nullptr, nullptr, IN_DIM, HID);
}

// round 17
// speedup vs baseline: 1.0573x; 1.0026x over previous
#include <cuda_runtime.h>
#include <cuda_bf16.h>
#include <math.h>
#include <stdint.h>

#define N_ROWS 32768
#define IN_DIM 768
#define HID 2048
#define OUT_DIM 256
#define KCODES 1024

typedef __nv_bfloat16 bf16;

// ---- scratch (device globals) ----
__device__ bf16 g_xs1[(size_t)N_ROWS * IN_DIM], g_xs2[(size_t)N_ROWS * IN_DIM], g_xs3[(size_t)N_ROWS * IN_DIM];
__device__ bf16 g_hs1[(size_t)N_ROWS * HID], g_hs2[(size_t)N_ROWS * HID], g_hs3[(size_t)N_ROWS * HID];
__device__ bf16 g_zs1[(size_t)N_ROWS * OUT_DIM], g_zs2[(size_t)N_ROWS * OUT_DIM], g_zs3[(size_t)N_ROWS * OUT_DIM];
__device__ bf16 g_w1a[(size_t)HID * IN_DIM], g_w1b[(size_t)HID * IN_DIM], g_w1c[(size_t)HID * IN_DIM];
__device__ bf16 g_w2a[(size_t)OUT_DIM * HID], g_w2b[(size_t)OUT_DIM * HID], g_w2c[(size_t)OUT_DIM * HID];
__device__ bf16 g_d1a[(size_t)HID * OUT_DIM], g_d1b[(size_t)HID * OUT_DIM], g_d1c[(size_t)HID * OUT_DIM];
__device__ bf16 g_d2a[(size_t)IN_DIM * HID], g_d2b[(size_t)IN_DIM * HID], g_d2c[(size_t)IN_DIM * HID];
__device__ bf16 g_et1[KCODES * OUT_DIM], g_et2[KCODES * OUT_DIM], g_et3[KCODES * OUT_DIM];
__device__ float2 g_part[(size_t)N_ROWS * (KCODES / 128)];
__device__ float g_emb2[KCODES];
__device__ float g_rownorm[N_ROWS];

// ---- helpers ----
__device__ __forceinline__ uint32_t smem_u32(const void* p) {
    uint32_t a;
    asm("{ .reg .u64 t; cvta.to.shared.u64 t, %1; cvt.u32.u64 %0, t; }" : "=r"(a) : "l"(p));
    return a;
}
__device__ __forceinline__ uint32_t lds32(uint32_t a) {
    uint32_t v; asm volatile("ld.shared.b32 %0, [%1];" : "=r"(v) : "r"(a)); return v;
}
__device__ __forceinline__ void cpasync16(uint32_t s, const void* g) {
    asm volatile("cp.async.cg.shared.global [%0], [%1], 16;" :: "r"(s), "l"(g));
}
__device__ __forceinline__ void mma16816(float* d, const uint32_t* a, const uint32_t* b) {
    asm volatile(
        "mma.sync.aligned.m16n8k16.row.col.f32.bf16.bf16.f32 "
        "{%0,%1,%2,%3}, {%4,%5,%6,%7}, {%8,%9}, {%0,%1,%2,%3};"
        : "+f"(d[0]), "+f"(d[1]), "+f"(d[2]), "+f"(d[3])
        : "r"(a[0]), "r"(a[1]), "r"(a[2]), "r"(a[3]), "r"(b[0]), "r"(b[1]));
}
__device__ __forceinline__ void split3(float v, bf16& b1, bf16& b2, bf16& b3) {
    b1 = __float2bfloat16(v);
    float r = v - __bfloat162float(b1);
    b2 = __float2bfloat16(r);
    b3 = __float2bfloat16(r - __bfloat162float(b2));
}
__device__ __forceinline__ uint32_t pack2(bf16 a, bf16 b) {
    return (uint32_t)__nv_bfloat16_raw(a).x | ((uint32_t)__nv_bfloat16_raw(b).x << 16);
}

// ============ kernel 1: encoder GEMM (NP=6, 32x32 warp tile, 2 CTAs/SM) ============
// CTA 128x64x32, 256 thr, 8 warps (4x2), 2-stage ring, per-chunk drain (12-mma chains).
// smem/CTA = 92160 -> 2 CTAs/SM; __launch_bounds__(256,2) caps regs at 128.
// EPI: 0 relu->splits, 1 none->fp32+splits
template<int EPI>
__global__ void __launch_bounds__(256, 2) gemmMMA(
    const bf16* __restrict__ A1, const bf16* __restrict__ A2, const bf16* __restrict__ A3,
    const bf16* __restrict__ B1, const bf16* __restrict__ B2, const bf16* __restrict__ B3,
    const float* __restrict__ bias,
    float* __restrict__ outF, bf16* __restrict__ O1, bf16* __restrict__ O2, bf16* __restrict__ O3,
    int N, int K)
{
    constexpr int TA = 128 * 80;          // A tile (128 rows)
    constexpr int TBB = 64 * 80;          // B tile (64 rows)
    constexpr int STG = 3 * TA + 3 * TBB; // 46080
    extern __shared__ char smem[];

    const int tid = threadIdx.x, lane = tid & 31, wid = tid >> 5;
    const int wm = wid >> 1, wn = wid & 1;             // 4 x 2 warp grid
    const int m0 = blockIdx.y * 128, n0 = blockIdx.x * 64;
    const uint32_t sbase = smem_u32(smem);
    const int lg = lane >> 2, lk = (lane & 3) * 2;

    const bf16* Asp[3] = {A1, A2, A3};
    const bf16* Bsp[3] = {B1, B2, B3};

    float sum[2][4][4];
    #pragma unroll
    for (int i = 0; i < 2; ++i)
        #pragma unroll
        for (int j = 0; j < 4; ++j)
            #pragma unroll
            for (int q = 0; q < 4; ++q) sum[i][j][q] = 0.0f;

    const int nc = K / 32;

    auto load_chunk = [&](int c) {
        const uint32_t sb = sbase + (c & 1) * STG;
        #pragma unroll
        for (int s = 0; s < 3; ++s) {
            const char* Ag = (const char*)Asp[s] + (size_t)m0 * K * 2 + (size_t)c * 64;
            const char* Bg = (const char*)Bsp[s] + (size_t)n0 * K * 2 + (size_t)c * 64;
            #pragma unroll
            for (int p = 0; p < 2; ++p) {           // A: 128 rows x 4 segs
                int idx = tid + p * 256;
                int r = idx >> 2, seg = idx & 3;
                cpasync16(sb + s * TA + r * 80 + seg * 16, Ag + (size_t)r * K * 2 + seg * 16);
            }
            {                                        // B: 64 rows x 4 segs = 256
                int r = tid >> 2, seg = tid & 3;
                cpasync16(sb + 3 * TA + s * TBB + r * 80 + seg * 16, Bg + (size_t)r * K * 2 + seg * 16);
            }
        }
    };

    load_chunk(0);
    asm volatile("cp.async.commit_group;" ::: "memory");

    const int bs_seq6[6] = {1, 1, 2, 0, 0, 0}, as_seq6[6] = {0, 1, 0, 1, 2, 0};

    for (int c = 0; c < nc; ++c) {
        if (c + 1 < nc) {
            load_chunk(c + 1);
            asm volatile("cp.async.commit_group;" ::: "memory");
            asm volatile("cp.async.wait_group 1;" ::: "memory");
        } else {
            asm volatile("cp.async.wait_group 0;" ::: "memory");
        }
        __syncthreads();

        const uint32_t sb = sbase + (c & 1) * STG;

        float accbuf[2][4][4];
        #pragma unroll
        for (int i = 0; i < 2; ++i)
            #pragma unroll
            for (int j = 0; j < 4; ++j)
                #pragma unroll
                for (int q = 0; q < 4; ++q) accbuf[i][j][q] = 0.0f;

        #pragma unroll
        for (int kh = 0; kh < 2; ++kh) {
            uint32_t af[3][2][4];
            #pragma unroll
            for (int s = 0; s < 3; ++s) {
                const uint32_t Ab = sb + s * TA;
                #pragma unroll
                for (int mf = 0; mf < 2; ++mf) {
                    uint32_t r = Ab + (wm * 32 + mf * 16 + lg) * 80 + (kh * 16 + lk) * 2;
                    af[s][mf][0] = lds32(r);
                    af[s][mf][1] = lds32(r + 8 * 80);
                    af[s][mf][2] = lds32(r + 16);
                    af[s][mf][3] = lds32(r + 8 * 80 + 16);
                }
            }
            uint32_t bfr[4][2];
            #pragma unroll
            for (int p = 0; p < 6; ++p) {
                const int bs = bs_seq6[p], as = as_seq6[p];
                const bool reload = (p == 0) || (bs_seq6[p] != bs_seq6[p - 1]);
                if (reload) {
                    const uint32_t Bb = sb + 3 * TA + bs * TBB;
                    #pragma unroll
                    for (int nf = 0; nf < 4; ++nf) {
                        uint32_t r = Bb + (wn * 32 + nf * 8 + lg) * 80 + (kh * 16 + lk) * 2;
                        bfr[nf][0] = lds32(r);
                        bfr[nf][1] = lds32(r + 16);
                    }
                }
                #pragma unroll
                for (int mf = 0; mf < 2; ++mf)
                    #pragma unroll
                    for (int nf = 0; nf < 4; ++nf)
                        mma16816(accbuf[mf][nf], af[as][mf], bfr[nf]);
            }
        }
        #pragma unroll
        for (int i = 0; i < 2; ++i)
            #pragma unroll
            for (int j = 0; j < 4; ++j)
                #pragma unroll
                for (int q = 0; q < 4; ++q)
                    sum[i][j][q] = __fadd_rn(sum[i][j][q], accbuf[i][j][q]);
        __syncthreads();
    }

    // ---- epilogue ----
    #pragma unroll
    for (int mf = 0; mf < 2; ++mf) {
        #pragma unroll
        for (int part = 0; part < 2; ++part) {
            const int row = m0 + wm * 32 + mf * 16 + lg + part * 8;
            #pragma unroll
            for (int nf = 0; nf < 4; ++nf) {
                const int col = n0 + wn * 32 + nf * 8 + lk;
                float f0 = sum[mf][nf][part * 2 + 0] + __ldg(bias + col);
                float f1 = sum[mf][nf][part * 2 + 1] + __ldg(bias + col + 1);
                if (EPI == 0) { f0 = fmaxf(f0, 0.0f); f1 = fmaxf(f1, 0.0f); }
                if (EPI == 1)
                    *(float2*)(outF + (size_t)row * N + col) = make_float2(f0, f1);
                bf16 a1, a2, a3, c1, c2, c3;
                split3(f0, a1, a2, a3);
                split3(f1, c1, c2, c3);
                const size_t o = (size_t)row * N + col;
                *(uint32_t*)(O1 + o) = pack2(a1, c1);
                *(uint32_t*)(O2 + o) = pack2(a2, c2);
                *(uint32_t*)(O3 + o) = pack2(a3, c3);
            }
        }
    }
}

// ============ kernel 2: 64x64-warp-tile 2-split GEMM (scores + decoder, no drain) ============
// CTA 128x128x32, 128 thr, 4 warps (2x2), warp tile 64x64, 2-stage ring, 2 CTAs/SM.
// EPI: 2 score->fused partial argmin, 3 sigmoid->splits, 4 none->fp32
template<int EPI>
__global__ void __launch_bounds__(128, 2) gemm64(
    const bf16* __restrict__ A1, const bf16* __restrict__ A2,
    const bf16* __restrict__ B1, const bf16* __restrict__ B2,
    const float* __restrict__ bias, const float* __restrict__ rowterm,
    float* __restrict__ outF, bf16* __restrict__ O1, bf16* __restrict__ O2, bf16* __restrict__ O3,
    float2* __restrict__ partOut,
    int N, int K)
{
    constexpr int TB = 128 * 80;
    constexpr int STG = 4 * TB;
    extern __shared__ char smem[];

    const int tid = threadIdx.x, lane = tid & 31, wid = tid >> 5;
    const int wm = wid >> 1, wn = wid & 1;
    const int m0 = blockIdx.y * 128, n0 = blockIdx.x * 128;
    const uint32_t sbase = smem_u32(smem);
    const int lg = lane >> 2, lk = (lane & 3) * 2;

    const bf16* Asp[2] = {A1, A2};
    const bf16* Bsp[2] = {B1, B2};

    float sum[4][8][4];
    #pragma unroll
    for (int i = 0; i < 4; ++i)
        #pragma unroll
        for (int j = 0; j < 8; ++j)
            #pragma unroll
            for (int q = 0; q < 4; ++q) sum[i][j][q] = 0.0f;

    const int nc = K / 32;

    auto load_chunk = [&](int c) {
        const uint32_t sb = sbase + (c & 1) * STG;
        #pragma unroll
        for (int s = 0; s < 2; ++s) {
            const char* Ag = (const char*)Asp[s] + (size_t)m0 * K * 2 + (size_t)c * 64;
            const char* Bg = (const char*)Bsp[s] + (size_t)n0 * K * 2 + (size_t)c * 64;
            #pragma unroll
            for (int p = 0; p < 4; ++p) {
                int idx = tid + p * 128;
                int r = idx >> 2, seg = idx & 3;
                cpasync16(sb + s * TB + r * 80 + seg * 16, Ag + (size_t)r * K * 2 + seg * 16);
                cpasync16(sb + (2 + s) * TB + r * 80 + seg * 16, Bg + (size_t)r * K * 2 + seg * 16);
            }
        }
    };

    load_chunk(0);
    asm volatile("cp.async.commit_group;" ::: "memory");

    const int bs_seq3[3] = {1, 0, 0}, as_seq3[3] = {0, 1, 0};

    for (int c = 0; c < nc; ++c) {
        if (c + 1 < nc) {
            load_chunk(c + 1);
            asm volatile("cp.async.commit_group;" ::: "memory");
            asm volatile("cp.async.wait_group 1;" ::: "memory");
        } else {
            asm volatile("cp.async.wait_group 0;" ::: "memory");
        }
        __syncthreads();

        const uint32_t sb = sbase + (c & 1) * STG;
        #pragma unroll
        for (int kh = 0; kh < 2; ++kh) {
            uint32_t af[2][4][4];
            #pragma unroll
            for (int s = 0; s < 2; ++s) {
                const uint32_t Ab = sb + s * TB;
                #pragma unroll
                for (int mf = 0; mf < 4; ++mf) {
                    uint32_t r = Ab + (wm * 64 + mf * 16 + lg) * 80 + (kh * 16 + lk) * 2;
                    af[s][mf][0] = lds32(r);
                    af[s][mf][1] = lds32(r + 8 * 80);
                    af[s][mf][2] = lds32(r + 16);
                    af[s][mf][3] = lds32(r + 8 * 80 + 16);
                }
            }
            uint32_t bfr[8][2];
            #pragma unroll
            for (int p = 0; p < 3; ++p) {
                const int bs = bs_seq3[p], as = as_seq3[p];
                const bool reload = (p == 0) || (bs_seq3[p] != bs_seq3[p - 1]);
                if (reload) {
                    const uint32_t Bb = sb + (2 + bs) * TB;
                    #pragma unroll
                    for (int nf = 0; nf < 8; ++nf) {
                        uint32_t r = Bb + (wn * 64 + nf * 8 + lg) * 80 + (kh * 16 + lk) * 2;
                        bfr[nf][0] = lds32(r);
                        bfr[nf][1] = lds32(r + 16);
                    }
                }
                #pragma unroll
                for (int mf = 0; mf < 4; ++mf)
                    #pragma unroll
                    for (int nf = 0; nf < 8; ++nf)
                        mma16816(sum[mf][nf], af[as][mf], bfr[nf]);
            }
        }
        __syncthreads();
    }

    // ---- epilogue ----
    if (EPI == 2) {
        float2* spart = (float2*)smem;
        #pragma unroll
        for (int mf = 0; mf < 4; ++mf) {
            #pragma unroll
            for (int part = 0; part < 2; ++part) {
                const int lrow = wm * 64 + mf * 16 + lg + part * 8;
                const float rt = __ldg(rowterm + m0 + lrow);
                float best = 3.4e38f;
                int bidx = 0;
                #pragma unroll
                for (int nf = 0; nf < 8; ++nf) {
                    const int col = n0 + wn * 64 + nf * 8 + lk;
                    float t0 = __fadd_rn(rt, __ldg(bias + col));
                    float t1 = __fadd_rn(rt, __ldg(bias + col + 1));
                    float d0 = __fmaf_rn(-2.0f, sum[mf][nf][part * 2 + 0], t0);
                    float d1 = __fmaf_rn(-2.0f, sum[mf][nf][part * 2 + 1], t1);
                    if (d0 < best) { best = d0; bidx = col; }
                    if (d1 < best) { best = d1; bidx = col + 1; }
                }
                #pragma unroll
                for (int off = 1; off <= 2; off <<= 1) {
                    float v2 = __shfl_xor_sync(0xffffffffu, best, off);
                    int i2 = __shfl_xor_sync(0xffffffffu, bidx, off);
                    if (v2 < best || (v2 == best && i2 < bidx)) { best = v2; bidx = i2; }
                }
                if ((lane & 3) == 0)
                    spart[wn * 128 + lrow] = make_float2(best, (float)bidx);
            }
        }
        __syncthreads();
        if (tid < 128) {
            float2 a = spart[tid], b = spart[128 + tid];
            float2 w = (b.x < a.x || (b.x == a.x && b.y < a.y)) ? b : a;
            partOut[(size_t)(m0 + tid) * (KCODES / 128) + blockIdx.x] = w;
        }
        return;
    }
    #pragma unroll
    for (int mf = 0; mf < 4; ++mf) {
        #pragma unroll
        for (int part = 0; part < 2; ++part) {
            const int row = m0 + wm * 64 + mf * 16 + lg + part * 8;
            #pragma unroll
            for (int nf = 0; nf < 8; ++nf) {
                const int col = n0 + wn * 64 + nf * 8 + lk;
                float f0 = sum[mf][nf][part * 2 + 0] + __ldg(bias + col);
                float f1 = sum[mf][nf][part * 2 + 1] + __ldg(bias + col + 1);
                if (EPI == 3) { f0 = 1.0f / (1.0f + expf(-f0)); f1 = 1.0f / (1.0f + expf(-f1)); }
                if (EPI == 4) {
                    *(float2*)(outF + (size_t)row * N + col) = make_float2(f0, f1);
                } else {
                    bf16 a1, a2, a3, c1, c2, c3;
                    split3(f0, a1, a2, a3);
                    split3(f1, c1, c2, c3);
                    const size_t o = (size_t)row * N + col;
                    *(uint32_t*)(O1 + o) = pack2(a1, c1);
                    *(uint32_t*)(O2 + o) = pack2(a2, c2);
                    *(uint32_t*)(O3 + o) = pack2(a3, c3);
                }
            }
        }
    }
}

// ---- elementwise split (n4 = n/4) ----
__global__ void __launch_bounds__(256) split_kernel(
    const float* __restrict__ in, bf16* __restrict__ o1, bf16* __restrict__ o2, bf16* __restrict__ o3, int n4)
{
    int i = blockIdx.x * 256 + threadIdx.x;
    if (i >= n4) return;
    float4 v = ((const float4*)in)[i];
    bf16 a1,a2,a3,b1,b2,b3,c1,c2,c3,d1,d2,d3;
    split3(v.x,a1,a2,a3); split3(v.y,b1,b2,b3); split3(v.z,c1,c2,c3); split3(v.w,d1,d2,d3);
    uint2 u;
    u.x = pack2(a1,b1); u.y = pack2(c1,d1); ((uint2*)o1)[i] = u;
    u.x = pack2(a2,b2); u.y = pack2(c2,d2); ((uint2*)o2)[i] = u;
    u.x = pack2(a3,b3); u.y = pack2(c3,d3); ((uint2*)o3)[i] = u;
}

// ---- W[K,N] -> T[N,K] with split ----
__global__ void __launch_bounds__(256) wsplit_kernel(
    const float* __restrict__ W, bf16* __restrict__ T1, bf16* __restrict__ T2, bf16* __restrict__ T3,
    int K, int N)
{
    __shared__ float t[32][33];
    int tx = threadIdx.x & 31, ty = threadIdx.x >> 5;
    int kb = blockIdx.y * 32, nb = blockIdx.x * 32;
    #pragma unroll
    for (int i = 0; i < 4; ++i)
        t[ty + 8*i][tx] = W[(size_t)(kb + ty + 8*i) * N + nb + tx];
    __syncthreads();
    #pragma unroll
    for (int i = 0; i < 4; ++i) {
        float v = t[tx][ty + 8*i];
        size_t o = (size_t)(nb + ty + 8*i) * K + kb + tx;
        bf16 b1,b2,b3; split3(v,b1,b2,b3);
        T1[o]=b1; T2[o]=b2; T3[o]=b3;
    }
}

__global__ void __launch_bounds__(256) emb2_kernel(const float* __restrict__ emb, float* __restrict__ out)
{
    int warp = (blockIdx.x * 256 + threadIdx.x) >> 5, lane = threadIdx.x & 31;
    if (warp >= KCODES) return;
    const float* e = emb + (size_t)warp * OUT_DIM;
    float s = 0.0f;
    for (int c = lane; c < OUT_DIM; c += 32) s = fmaf(e[c], e[c], s);
    for (int off = 16; off; off >>= 1) s += __shfl_down_sync(0xffffffffu, s, off);
    if (lane == 0) out[warp] = s;
}

__global__ void __launch_bounds__(256) rownorm_kernel(const float* __restrict__ z, float* __restrict__ out)
{
    int row = (blockIdx.x * 256 + threadIdx.x) >> 5, lane = threadIdx.x & 31;
    if (row >= N_ROWS) return;
    const float* zr = z + (size_t)row * OUT_DIM;
    float s = 0.0f;
    for (int c = lane; c < OUT_DIM; c += 32) s = fmaf(zr[c], zr[c], s);
    for (int off = 16; off; off >>= 1) s += __shfl_down_sync(0xffffffffu, s, off);
    if (lane == 0) out[row] = s;
}

// ---- final argmin over 8 partials + gather + residual / decoder-input fusion ----
__global__ void __launch_bounds__(256) argmin_kernel(
    const float2* __restrict__ part, const float* __restrict__ ze, const float* __restrict__ emb,
    float* __restrict__ n_out, float* __restrict__ zq_out, float* __restrict__ zenext_out,
    float* __restrict__ rownorm_out, bf16* __restrict__ Z1, bf16* __restrict__ Z2, bf16* __restrict__ Z3,
    const float* __restrict__ decbase)
{
    int row = (blockIdx.x * 256 + threadIdx.x) >> 5, lane = threadIdx.x & 31;
    if (row >= N_ROWS) return;

    float best = 3.4e38f;
    int bidx = KCODES;
    if (lane < (KCODES / 128)) {
        float2 p = part[(size_t)row * (KCODES / 128) + lane];
        best = p.x;
        bidx = (int)p.y;
    }
    #pragma unroll
    for (int off = 4; off; off >>= 1) {
        float v2 = __shfl_down_sync(0xffffffffu, best, off);
        int i2 = __shfl_down_sync(0xffffffffu, bidx, off);
        if (v2 < best || (v2 == best && i2 < bidx)) { best = v2; bidx = i2; }
    }
    bidx = __shfl_sync(0xffffffffu, bidx, 0);
    if (lane == 0) n_out[row] = (float)bidx;

    const float* e = emb + (size_t)bidx * OUT_DIM;
    const float* z = ze + (size_t)row * OUT_DIM;
    float* zq = zq_out + (size_t)row * OUT_DIM;
    const size_t ob = (size_t)row * OUT_DIM;
    if (zenext_out) {
        float* zn = zenext_out + ob;
        float nrm = 0.0f;
        for (int c = lane; c < OUT_DIM; c += 32) {
            float ev = e[c], r = z[c] - ev;
            zq[c] = ev; zn[c] = r;
            bf16 b1,b2,b3; split3(r,b1,b2,b3);
            Z1[ob+c]=b1; Z2[ob+c]=b2; Z3[ob+c]=b3;
            nrm = fmaf(r, r, nrm);
        }
        for (int off = 16; off; off >>= 1) nrm += __shfl_down_sync(0xffffffffu, nrm, off);
        if (lane == 0) rownorm_out[row] = nrm;
    } else {
        const float* db = decbase + ob;
        for (int c = lane; c < OUT_DIM; c += 32) {
            float ev = e[c];
            zq[c] = ev;
            float d = db[c] - (z[c] - ev);
            bf16 b1,b2,b3; split3(d,b1,b2,b3);
            Z1[ob+c]=b1; Z2[ob+c]=b2; Z3[ob+c]=b3;
        }
    }
}

// ---- launch ----
extern "C" void kernel_launch(void* const* d_in, const int* in_sizes, int n_in,
                              void* d_out, int out_size)
{
    const float* x    = (const float*)d_in[0];
    const float* We1  = (const float*)d_in[1];
    const float* be1  = (const float*)d_in[2];
    const float* We2  = (const float*)d_in[3];
    const float* be2  = (const float*)d_in[4];
    const float* Wd1  = (const float*)d_in[5];
    const float* bd1  = (const float*)d_in[6];
    const float* Wd2  = (const float*)d_in[7];
    const float* bd2  = (const float*)d_in[8];
    const float* emb1 = (const float*)d_in[9];
    const float* emb2c= (const float*)d_in[10];
    const float* emb3c= (const float*)d_in[11];

    float* out = (float*)d_out;
    float* recon = out;
    float* ze1 = recon + (size_t)N_ROWS * IN_DIM;
    float* ze2 = ze1 + (size_t)N_ROWS * OUT_DIM;
    float* ze3 = ze2 + (size_t)N_ROWS * OUT_DIM;
    float* zq1 = ze3 + (size_t)N_ROWS * OUT_DIM;
    float* zq2 = zq1 + (size_t)N_ROWS * OUT_DIM;
    float* zq3 = zq2 + (size_t)N_ROWS * OUT_DIM;
    float* n1  = zq3 + (size_t)N_ROWS * OUT_DIM;
    float* n2  = n1 + N_ROWS;
    float* n3  = n2 + N_ROWS;

    bf16 *xs1,*xs2,*xs3,*hs1,*hs2,*hs3,*zs1,*zs2,*zs3;
    bf16 *w1a,*w1b,*w1c,*w2a,*w2b,*w2c,*d1a,*d1b,*d1c,*d2a,*d2b,*d2c,*et1,*et2,*et3;
    float *e2,*rn;
    float2 *pt;
    cudaGetSymbolAddress((void**)&xs1, g_xs1); cudaGetSymbolAddress((void**)&xs2, g_xs2);
    cudaGetSymbolAddress((void**)&xs3, g_xs3); cudaGetSymbolAddress((void**)&hs1, g_hs1);
    cudaGetSymbolAddress((void**)&hs2, g_hs2); cudaGetSymbolAddress((void**)&hs3, g_hs3);
    cudaGetSymbolAddress((void**)&zs1, g_zs1); cudaGetSymbolAddress((void**)&zs2, g_zs2);
    cudaGetSymbolAddress((void**)&zs3, g_zs3);
    cudaGetSymbolAddress((void**)&w1a, g_w1a); cudaGetSymbolAddress((void**)&w1b, g_w1b);
    cudaGetSymbolAddress((void**)&w1c, g_w1c); cudaGetSymbolAddress((void**)&w2a, g_w2a);
    cudaGetSymbolAddress((void**)&w2b, g_w2b); cudaGetSymbolAddress((void**)&w2c, g_w2c);
    cudaGetSymbolAddress((void**)&d1a, g_d1a); cudaGetSymbolAddress((void**)&d1b, g_d1b);
    cudaGetSymbolAddress((void**)&d1c, g_d1c); cudaGetSymbolAddress((void**)&d2a, g_d2a);
    cudaGetSymbolAddress((void**)&d2b, g_d2b); cudaGetSymbolAddress((void**)&d2c, g_d2c);
    cudaGetSymbolAddress((void**)&et1, g_et1); cudaGetSymbolAddress((void**)&et2, g_et2);
    cudaGetSymbolAddress((void**)&et3, g_et3); cudaGetSymbolAddress((void**)&pt, g_part);
    cudaGetSymbolAddress((void**)&e2, g_emb2); cudaGetSymbolAddress((void**)&rn, g_rownorm);

    const int SMEME = 2 * (3 * 128 * 80 + 3 * 64 * 80);   // 92160 -> 2 CTAs/SM
    const int SMEM64 = 2 * (4 * 128 * 80);                // 81920
    cudaFuncSetAttribute(gemmMMA<0>, cudaFuncAttributeMaxDynamicSharedMemorySize, SMEME);
    cudaFuncSetAttribute(gemmMMA<1>, cudaFuncAttributeMaxDynamicSharedMemorySize, SMEME);
    cudaFuncSetAttribute(gemm64<2>, cudaFuncAttributeMaxDynamicSharedMemorySize, SMEM64);
    cudaFuncSetAttribute(gemm64<3>, cudaFuncAttributeMaxDynamicSharedMemorySize, SMEM64);
    cudaFuncSetAttribute(gemm64<4>, cudaFuncAttributeMaxDynamicSharedMemorySize, SMEM64);

    const dim3 blk(256), dblk(128);
    const int MTILES = N_ROWS / 128;

    // launch index 3 = enc1 GEMM (profiled by ncu capture)
    split_kernel<<<(N_ROWS * IN_DIM / 4 + 255) / 256, blk>>>(x, xs1, xs2, xs3, N_ROWS * IN_DIM / 4);   // 0
    wsplit_kernel<<<dim3(HID / 32, IN_DIM / 32), blk>>>(We1, w1a, w1b, w1c, IN_DIM, HID);              // 1
    wsplit_kernel<<<dim3(OUT_DIM / 32, HID / 32), blk>>>(We2, w2a, w2b, w2c, HID, OUT_DIM);            // 2
    gemmMMA<0><<<dim3(HID / 64, MTILES), blk, SMEME>>>(                                                 // 3
        xs1, xs2, xs3, w1a, w1b, w1c, be1, nullptr, hs1, hs2, hs3, HID, IN_DIM);
    gemmMMA<1><<<dim3(OUT_DIM / 64, MTILES), blk, SMEME>>>(
        hs1, hs2, hs3, w2a, w2b, w2c, be2, ze1, zs1, zs2, zs3, OUT_DIM, HID);

    // stage 1 (score GEMM with fused partial argmin)
    rownorm_kernel<<<N_ROWS / 8, blk>>>(ze1, rn);
    split_kernel<<<(KCODES * OUT_DIM / 4 + 255) / 256, blk>>>(emb1, et1, et2, et3, KCODES * OUT_DIM / 4);
    emb2_kernel<<<KCODES / 8, blk>>>(emb1, e2);
    gemm64<2><<<dim3(KCODES / 128, MTILES), dblk, SMEM64>>>(
        zs1, zs2, et1, et2, e2, rn, nullptr, nullptr, nullptr, nullptr, pt, KCODES, OUT_DIM);
    argmin_kernel<<<N_ROWS / 8, blk>>>(pt, ze1, emb1, n1, zq1, ze2, rn, zs1, zs2, zs3, nullptr);

    // stage 2
    split_kernel<<<(KCODES * OUT_DIM / 4 + 255) / 256, blk>>>(emb2c, et1, et2, et3, KCODES * OUT_DIM / 4);
    emb2_kernel<<<KCODES / 8, blk>>>(emb2c, e2);
    gemm64<2><<<dim3(KCODES / 128, MTILES), dblk, SMEM64>>>(
        zs1, zs2, et1, et2, e2, rn, nullptr, nullptr, nullptr, nullptr, pt, KCODES, OUT_DIM);
    argmin_kernel<<<N_ROWS / 8, blk>>>(pt, ze2, emb2c, n2, zq2, ze3, rn, zs1, zs2, zs3, nullptr);

    // stage 3 (fused: emits decoder-input splits = zq1+zq2+zq3 via ze1 - r3)
    split_kernel<<<(KCODES * OUT_DIM / 4 + 255) / 256, blk>>>(emb3c, et1, et2, et3, KCODES * OUT_DIM / 4);
    emb2_kernel<<<KCODES / 8, blk>>>(emb3c, e2);
    gemm64<2><<<dim3(KCODES / 128, MTILES), dblk, SMEM64>>>(
        zs1, zs2, et1, et2, e2, rn, nullptr, nullptr, nullptr, nullptr, pt, KCODES, OUT_DIM);
    argmin_kernel<<<N_ROWS / 8, blk>>>(pt, ze3, emb3c, n3, zq3, nullptr, nullptr, zs1, zs2, zs3, ze1);

    // decoder (64x64-tile 2-split GEMMs)
    wsplit_kernel<<<dim3(HID / 32, OUT_DIM / 32), blk>>>(Wd1, d1a, d1b, d1c, OUT_DIM, HID);
    gemm64<3><<<dim3(HID / 128, MTILES), dblk, SMEM64>>>(
        zs1, zs2, d1a, d1b, bd1, nullptr, nullptr, hs1, hs2, hs3, nullptr, HID, OUT_DIM);
    wsplit_kernel<<<dim3(IN_DIM / 32, HID / 32), blk>>>(Wd2, d2a, d2b, d2c, HID, IN_DIM);
    gemm64<4><<<dim3(IN_DIM / 128, MTILES), dblk, SMEM64>>>(
        hs1, hs2, d2a, d2b, bd2, nullptr, recon, nullptr, nullptr, nullptr, nullptr, IN_DIM, HID);
}